// round 15
// baseline (speedup 1.0000x reference)
#include <cuda_runtime.h>
#include <cuda_bf16.h>
#include <cstdint>
#include <math.h>

#define LSEQ 4096
#define EMB  1024
#define NH   16
#define DH   64
#define QKV3 3072

// Scratch (allocation-free rule: device globals)
__device__ float g_qkv[LSEQ * QKV3];   // [L, 3E]
__device__ float g_attn[LSEQ * EMB];   // [L, E] (tf32-rounded by attn epilogue)
__device__ float g_xt[LSEQ * EMB];     // x tf32-rounded
__device__ float g_wqt[QKV3 * EMB];    // w_qkv tf32-rounded
__device__ float g_wot[EMB * EMB];     // w_out tf32-rounded
__device__ __nv_bfloat16 g_qh[LSEQ * EMB], g_ql[LSEQ * EMB];   // Q*scale*log2e hi/lo [L,E]
__device__ __nv_bfloat16 g_kh[LSEQ * EMB], g_kl[LSEQ * EMB];   // K hi/lo [L,E]
__device__ __nv_bfloat16 g_vth[EMB * LSEQ], g_vtl[EMB * LSEQ]; // V^T hi/lo [E,L]

// ===========================================================================
// PTX helpers (non-'a' features only: ldmatrix / mma.sync / cp.async / cvt)
// ===========================================================================
__device__ __forceinline__ uint32_t smem_u32(const void* p) {
    uint32_t a;
    asm("{ .reg .u64 t; cvta.to.shared.u64 t, %1; cvt.u32.u64 %0, t; }" : "=r"(a) : "l"(p));
    return a;
}
__device__ __forceinline__ uint32_t f2tf32(float f) {
    uint32_t r; asm("cvt.rna.tf32.f32 %0, %1;" : "=r"(r) : "f"(f)); return r;
}
__device__ __forceinline__ float ex2f(float x) {
    float r; asm("ex2.approx.ftz.f32 %0, %1;" : "=f"(r) : "f"(x)); return r;
}
__device__ __forceinline__ void ldmatrix_x4(uint32_t& r0, uint32_t& r1, uint32_t& r2, uint32_t& r3,
                                            uint32_t addr) {
    asm volatile("ldmatrix.sync.aligned.m8n8.x4.shared.b16 {%0,%1,%2,%3}, [%4];"
                 : "=r"(r0), "=r"(r1), "=r"(r2), "=r"(r3) : "r"(addr));
}
__device__ __forceinline__ void ldmatrix_x2(uint32_t& r0, uint32_t& r1, uint32_t addr) {
    asm volatile("ldmatrix.sync.aligned.m8n8.x2.shared.b16 {%0,%1}, [%2];"
                 : "=r"(r0), "=r"(r1) : "r"(addr));
}
__device__ __forceinline__ void mma_tf32(float& c0, float& c1, float& c2, float& c3,
                                         uint32_t a0, uint32_t a1, uint32_t a2, uint32_t a3,
                                         uint32_t b0, uint32_t b1) {
    asm volatile(
        "mma.sync.aligned.m16n8k8.row.col.f32.tf32.tf32.f32 "
        "{%0,%1,%2,%3}, {%4,%5,%6,%7}, {%8,%9}, {%0,%1,%2,%3};"
        : "+f"(c0), "+f"(c1), "+f"(c2), "+f"(c3)
        : "r"(a0), "r"(a1), "r"(a2), "r"(a3), "r"(b0), "r"(b1));
}
__device__ __forceinline__ void mma_bf16(float* c,
                                         uint32_t a0, uint32_t a1, uint32_t a2, uint32_t a3,
                                         uint32_t b0, uint32_t b1) {
    asm volatile(
        "mma.sync.aligned.m16n8k16.row.col.f32.bf16.bf16.f32 "
        "{%0,%1,%2,%3}, {%4,%5,%6,%7}, {%8,%9}, {%0,%1,%2,%3};"
        : "+f"(c[0]), "+f"(c[1]), "+f"(c[2]), "+f"(c[3])
        : "r"(a0), "r"(a1), "r"(a2), "r"(a3), "r"(b0), "r"(b1));
}
__device__ __forceinline__ void bsplit(float x, __nv_bfloat16& h, __nv_bfloat16& l) {
    h = __float2bfloat16(x);
    l = __float2bfloat16(x - __bfloat162float(h));
}
__device__ __forceinline__ void bsplit2(float x0, float x1, uint32_t& hi, uint32_t& lo) {
    __nv_bfloat16 h0, l0, h1, l1;
    bsplit(x0, h0, l0);
    bsplit(x1, h1, l1);
    hi = ((uint32_t)__bfloat16_as_ushort(h1) << 16) | (uint32_t)__bfloat16_as_ushort(h0);
    lo = ((uint32_t)__bfloat16_as_ushort(l1) << 16) | (uint32_t)__bfloat16_as_ushort(l0);
}
__device__ __forceinline__ void cp16(uint32_t dst, const void* src) {
    asm volatile("cp.async.cg.shared.global [%0], [%1], 16;" :: "r"(dst), "l"(src));
}
__device__ __forceinline__ void cp_commit() {
    asm volatile("cp.async.commit_group;" ::: "memory");
}
template <int N>
__device__ __forceinline__ void cp_wait() {
    asm volatile("cp.async.wait_group %0;" :: "n"(N) : "memory");
}

// ===========================================================================
// tf32 pre-rounding: out[i] = cvt.rna.tf32(in[i]) (float4 granularity)
// ===========================================================================
__global__ __launch_bounds__(256) void tf32_round(const float* __restrict__ in,
                                                  float* __restrict__ out, int n4) {
    int idx = blockIdx.x * 256 + threadIdx.x;
    if (idx >= n4) return;
    float4 v = reinterpret_cast<const float4*>(in)[idx];
    v.x = __uint_as_float(f2tf32(v.x));
    v.y = __uint_as_float(f2tf32(v.y));
    v.z = __uint_as_float(f2tf32(v.z));
    v.w = __uint_as_float(f2tf32(v.w));
    reinterpret_cast<float4*>(out)[idx] = v;
}

// ===========================================================================
// Tensor-core tf32 GEMM v4: THREE-stage cp.async ring (hides the ~600-cyc
// global latency that the 2-stage version exposed every chunk), single
// barrier per chunk, inputs pre-rounded to tf32.
// C[m][n] = sum_k A[m][k]*B[n][k]; 128x128 CTA tile, BK=32.
// Smem: 3 A-bufs + 3 B-bufs x 18KB = 108KB; 2 CTAs/SM (216KB <= 228KB).
// ===========================================================================
#define GPAD 36
#define GEMM_BUF (128 * GPAD)
#define GEMM_SMEM (6 * GEMM_BUF * 4)

__global__ __launch_bounds__(256, 2) void gemm_mma(const float* __restrict__ A,
                                                   const float* __restrict__ B,
                                                   float* __restrict__ C,
                                                   int M, int N, int K) {
    extern __shared__ float gsm[];
    const int tid = threadIdx.x;
    const int t = tid & 31;
    const int wid = tid >> 5;
    const int wm = wid >> 2;
    const int wn = wid & 3;
    const int rbase = blockIdx.y * 128;
    const int cbase = blockIdx.x * 128;
    const int nchunks = K >> 5;

    const uint32_t sm_b = smem_u32(gsm);

    const int a_rl = (t & 7) + ((t >> 3) & 1) * 8;
    const int a_cb = ((t >> 4) & 1) * 16;
    const int b_rl = (t & 7);
    const int b_cb = ((t >> 3) & 1) * 16;

    float c[4][4][4];
#pragma unroll
    for (int mf = 0; mf < 4; mf++)
#pragma unroll
        for (int nf = 0; nf < 4; nf++)
#pragma unroll
            for (int v = 0; v < 4; v++) c[mf][nf][v] = 0.f;

    const float* Ag = A + (size_t)rbase * K;
    const float* Bg = B + (size_t)cbase * K;

    // prologue: issue chunks 0 and 1 into stages 0 and 1 (separate groups)
#pragma unroll
    for (int pc = 0; pc < 2; pc++) {
        const uint32_t ab = sm_b + pc * GEMM_BUF * 4;
        const uint32_t bb = sm_b + (3 + pc) * GEMM_BUF * 4;
#pragma unroll
        for (int i = 0; i < 4; i++) {
            int fi = tid + i * 256;
            int row = fi >> 3, c4 = (fi & 7) << 2;
            uint32_t off = (uint32_t)((row * GPAD + c4) * 4);
            cp16(ab + off, Ag + (size_t)row * K + pc * 32 + c4);
            cp16(bb + off, Bg + (size_t)row * K + pc * 32 + c4);
        }
        cp_commit();
    }

    for (int ck = 0; ck < nchunks; ck++) {
        const int s = ck % 3;
        // chunk ck was issued 2 iterations ago; allow the ck+1 group to float
        if (ck + 1 < nchunks) cp_wait<1>();
        else                  cp_wait<0>();
        __syncthreads();
        // issue chunk ck+2 into stage (ck+2)%3 (last computed at ck-1; all
        // warps passed the barrier above after finishing it)
        if (ck + 2 < nchunks) {
            const int k2 = (ck + 2) * 32;
            const int s2 = (ck + 2) % 3;
            const uint32_t ab = sm_b + s2 * GEMM_BUF * 4;
            const uint32_t bb = sm_b + (3 + s2) * GEMM_BUF * 4;
#pragma unroll
            for (int i = 0; i < 4; i++) {
                int fi = tid + i * 256;
                int row = fi >> 3, c4 = (fi & 7) << 2;
                uint32_t off = (uint32_t)((row * GPAD + c4) * 4);
                cp16(ab + off, Ag + (size_t)row * K + k2 + c4);
                cp16(bb + off, Bg + (size_t)row * K + k2 + c4);
            }
            cp_commit();
        }

        const uint32_t As_b = sm_b + s * GEMM_BUF * 4;
        const uint32_t Bs_b = sm_b + (3 + s) * GEMM_BUF * 4;
#pragma unroll
        for (int ks = 0; ks < 4; ks++) {
            uint32_t af[4][4], bf[4][2];
#pragma unroll
            for (int mf = 0; mf < 4; mf++) {
                int row = wm * 64 + mf * 16 + a_rl;
                uint32_t addr = As_b + (uint32_t)(row * GPAD * 4 + ks * 32 + a_cb);
                ldmatrix_x4(af[mf][0], af[mf][1], af[mf][2], af[mf][3], addr);
            }
#pragma unroll
            for (int nf = 0; nf < 4; nf++) {
                int row = wn * 32 + nf * 8 + b_rl;
                uint32_t addr = Bs_b + (uint32_t)(row * GPAD * 4 + ks * 32 + b_cb);
                ldmatrix_x2(bf[nf][0], bf[nf][1], addr);
            }
#pragma unroll
            for (int mf = 0; mf < 4; mf++)
#pragma unroll
                for (int nf = 0; nf < 4; nf++)
                    mma_tf32(c[mf][nf][0], c[mf][nf][1], c[mf][nf][2], c[mf][nf][3],
                             af[mf][0], af[mf][1], af[mf][2], af[mf][3],
                             bf[nf][0], bf[nf][1]);
        }
    }

    const int g = t >> 2;
    const int tg = t & 3;
#pragma unroll
    for (int mf = 0; mf < 4; mf++) {
        int row0 = rbase + wm * 64 + mf * 16 + g;
#pragma unroll
        for (int nf = 0; nf < 4; nf++) {
            int col = cbase + wn * 32 + nf * 8 + 2 * tg;
            float2 lo = make_float2(c[mf][nf][0], c[mf][nf][1]);
            float2 hi = make_float2(c[mf][nf][2], c[mf][nf][3]);
            *reinterpret_cast<float2*>(&C[(size_t)row0 * N + col]) = lo;
            *reinterpret_cast<float2*>(&C[(size_t)(row0 + 8) * N + col]) = hi;
        }
    }
}

// ===========================================================================
// Prep: split Q (scaled by 0.125*log2(e) for base-2 softmax) and K into hi/lo
// ===========================================================================
#define QSCALE 0.18033688011112042f   // 0.125 * log2(e)

__global__ __launch_bounds__(256) void prep_qk(const float* __restrict__ qkv,
                                               __nv_bfloat16* __restrict__ qh,
                                               __nv_bfloat16* __restrict__ ql,
                                               __nv_bfloat16* __restrict__ kh,
                                               __nv_bfloat16* __restrict__ kl) {
    int idx = blockIdx.x * 256 + threadIdx.x;
    int l = idx >> 8;
    int e = (idx & 255) << 2;
    float4 q = *reinterpret_cast<const float4*>(qkv + (size_t)l * QKV3 + e);
    float4 k = *reinterpret_cast<const float4*>(qkv + (size_t)l * QKV3 + EMB + e);
    size_t o = (size_t)l * EMB + e;
    float qs[4] = {q.x * QSCALE, q.y * QSCALE, q.z * QSCALE, q.w * QSCALE};
    float ks[4] = {k.x, k.y, k.z, k.w};
#pragma unroll
    for (int j = 0; j < 4; j++) {
        __nv_bfloat16 h, lo;
        bsplit(qs[j], h, lo);
        qh[o + j] = h; ql[o + j] = lo;
        bsplit(ks[j], h, lo);
        kh[o + j] = h; kl[o + j] = lo;
    }
}

__global__ __launch_bounds__(256) void prep_vt(const float* __restrict__ qkv,
                                               __nv_bfloat16* __restrict__ vth,
                                               __nv_bfloat16* __restrict__ vtl) {
    __shared__ float tile[32][33];
    const int e0 = blockIdx.x * 32;
    const int l0 = blockIdx.y * 32;
    const int tx = threadIdx.x, ty = threadIdx.y;
#pragma unroll
    for (int j = 0; j < 4; j++)
        tile[ty * 4 + j][tx] = qkv[(size_t)(l0 + ty * 4 + j) * QKV3 + 2 * EMB + e0 + tx];
    __syncthreads();
#pragma unroll
    for (int j = 0; j < 4; j++) {
        float v = tile[tx][ty * 4 + j];
        __nv_bfloat16 h, lo;
        bsplit(v, h, lo);
        size_t o = (size_t)(e0 + ty * 4 + j) * LSEQ + l0 + tx;
        vth[o] = h; vtl[o] = lo;
    }
}

// ===========================================================================
// Flash attention v7 (unchanged from R14): fixed-offset softmax, 4 warps x
// 32 Q rows, register-resident P, cp.async double-buffered KV, exp/bsplit
// interleaved into PV, single barrier per tile.
// ===========================================================================
#define S_QL_OFF 16384
#define KV_OFF   32768
#define KV_STRIDE 32768
#define KL_OFF   8192
#define V_OFF    16384
#define VL_OFF   8192
#define ATT_SMEM 98304
#define FIXED_M  40.0f

__global__ __launch_bounds__(128, 2) void attn_mma(
    const __nv_bfloat16* __restrict__ qh_g, const __nv_bfloat16* __restrict__ ql_g,
    const __nv_bfloat16* __restrict__ kh_g, const __nv_bfloat16* __restrict__ kl_g,
    const __nv_bfloat16* __restrict__ vth_g, const __nv_bfloat16* __restrict__ vtl_g,
    float* __restrict__ out) {
    extern __shared__ char sm[];
    const uint32_t sb = smem_u32(sm);
    const int tid = threadIdx.x;
    const int t = tid & 31, w = tid >> 5;
    const int h = blockIdx.y;
    const int q0 = blockIdx.x * 128;
    const int g = t >> 2, tg = t & 3;

    const int a_rl = (t & 7) + ((t >> 3) & 1) * 8;
    const int a_cb = ((t >> 4) & 1) * 16;
    const int b_rl = ((t >> 4) & 1) * 8 + (t & 7);
    const int b_cb = ((t >> 3) & 1) * 16;

    // ---- prologue: issue Q + KV tile 0 as one group ----
#pragma unroll
    for (int i = 0; i < 8; i++) {
        int slot = tid + i * 128;
        int row = slot >> 3, ch = slot & 7;
        uint32_t dst = (uint32_t)(row * 128 + ((ch * 16) ^ ((row & 7) * 16)));
        size_t src = (size_t)(q0 + row) * EMB + h * 64 + ch * 8;
        cp16(sb + dst, qh_g + src);
        cp16(sb + S_QL_OFF + dst, ql_g + src);
    }
#pragma unroll
    for (int i = 0; i < 4; i++) {
        int slot = tid + i * 128;
        int row = slot >> 3, ch = slot & 7;
        uint32_t dst = (uint32_t)(row * 128 + ((ch * 16) ^ ((row & 7) * 16)));
        size_t ksrc = (size_t)row * EMB + h * 64 + ch * 8;
        size_t vsrc = (size_t)(h * 64 + row) * LSEQ + ch * 8;
        uint32_t kb = sb + KV_OFF;
        cp16(kb + dst, kh_g + ksrc);
        cp16(kb + KL_OFF + dst, kl_g + ksrc);
        cp16(kb + V_OFF + dst, vth_g + vsrc);
        cp16(kb + V_OFF + VL_OFF + dst, vtl_g + vsrc);
    }
    cp_commit();

    // l accumulators (per-thread partial sums, reduced once at the end)
    float lacc0[2] = {0.f, 0.f}, lacc1[2] = {0.f, 0.f};
    float o[2][8][4];
#pragma unroll
    for (int mf = 0; mf < 2; mf++)
#pragma unroll
        for (int nf = 0; nf < 8; nf++)
#pragma unroll
            for (int v = 0; v < 4; v++) o[mf][nf][v] = 0.f;

    const int NT = LSEQ / 64;
    for (int kt = 0; kt < NT; kt++) {
        const int b = kt & 1;
        const uint32_t kvb = sb + KV_OFF + b * KV_STRIDE;

        cp_wait<0>();
        __syncthreads();
        if (kt + 1 < NT) {
            const int kv1 = (kt + 1) * 64;
            const uint32_t nb = sb + KV_OFF + (b ^ 1) * KV_STRIDE;
#pragma unroll
            for (int i = 0; i < 4; i++) {
                int slot = tid + i * 128;
                int row = slot >> 3, ch = slot & 7;
                uint32_t dst = (uint32_t)(row * 128 + ((ch * 16) ^ ((row & 7) * 16)));
                size_t ksrc = (size_t)(kv1 + row) * EMB + h * 64 + ch * 8;
                size_t vsrc = (size_t)(h * 64 + row) * LSEQ + kv1 + ch * 8;
                cp16(nb + dst, kh_g + ksrc);
                cp16(nb + KL_OFF + dst, kl_g + ksrc);
                cp16(nb + V_OFF + dst, vth_g + vsrc);
                cp16(nb + V_OFF + VL_OFF + dst, vtl_g + vsrc);
            }
            cp_commit();
        }

        // ---- S = Q K^T (3-term bf16), warp rows = w*32 .. +31 ----
        float s[2][8][4];
#pragma unroll
        for (int mf = 0; mf < 2; mf++)
#pragma unroll
            for (int nf = 0; nf < 8; nf++)
#pragma unroll
                for (int v = 0; v < 4; v++) s[mf][nf][v] = 0.f;

#pragma unroll
        for (int ks = 0; ks < 4; ks++) {
            uint32_t qh_f[2][4], ql_f[2][4];
#pragma unroll
            for (int mf = 0; mf < 2; mf++) {
                int qrow = w * 32 + mf * 16 + a_rl;
                uint32_t qaddr = sb + (uint32_t)(qrow * 128 + ((ks * 32 + a_cb) ^ ((qrow & 7) * 16)));
                ldmatrix_x4(qh_f[mf][0], qh_f[mf][1], qh_f[mf][2], qh_f[mf][3], qaddr);
                ldmatrix_x4(ql_f[mf][0], ql_f[mf][1], ql_f[mf][2], ql_f[mf][3], qaddr + S_QL_OFF);
            }
#pragma unroll
            for (int p = 0; p < 4; p++) {
                int krow = p * 16 + b_rl;
                uint32_t kaddr = kvb + (uint32_t)(krow * 128 + ((ks * 32 + b_cb) ^ ((krow & 7) * 16)));
                uint32_t kh0, kh1, kh2, kh3, klo0, klo1, klo2, klo3;
                ldmatrix_x4(kh0, kh1, kh2, kh3, kaddr);
                ldmatrix_x4(klo0, klo1, klo2, klo3, kaddr + KL_OFF);
#pragma unroll
                for (int mf = 0; mf < 2; mf++) {
                    mma_bf16(s[mf][2 * p], qh_f[mf][0], qh_f[mf][1], qh_f[mf][2], qh_f[mf][3], kh0, kh1);
                    mma_bf16(s[mf][2 * p], qh_f[mf][0], qh_f[mf][1], qh_f[mf][2], qh_f[mf][3], klo0, klo1);
                    mma_bf16(s[mf][2 * p], ql_f[mf][0], ql_f[mf][1], ql_f[mf][2], ql_f[mf][3], kh0, kh1);
                    mma_bf16(s[mf][2 * p + 1], qh_f[mf][0], qh_f[mf][1], qh_f[mf][2], qh_f[mf][3], kh2, kh3);
                    mma_bf16(s[mf][2 * p + 1], qh_f[mf][0], qh_f[mf][1], qh_f[mf][2], qh_f[mf][3], klo2, klo3);
                    mma_bf16(s[mf][2 * p + 1], ql_f[mf][0], ql_f[mf][1], ql_f[mf][2], ql_f[mf][3], kh2, kh3);
                }
            }
        }

        // ---- PV with fixed-offset exp2 interleaved per k-step ----
#pragma unroll
        for (int ks = 0; ks < 4; ks++) {
            uint32_t ah[2][4], al[2][4];
#pragma unroll
            for (int mf = 0; mf < 2; mf++) {
                float e0 = ex2f(s[mf][2 * ks][0] - FIXED_M);
                float e1 = ex2f(s[mf][2 * ks][1] - FIXED_M);
                float e2 = ex2f(s[mf][2 * ks][2] - FIXED_M);
                float e3 = ex2f(s[mf][2 * ks][3] - FIXED_M);
                float e4 = ex2f(s[mf][2 * ks + 1][0] - FIXED_M);
                float e5 = ex2f(s[mf][2 * ks + 1][1] - FIXED_M);
                float e6 = ex2f(s[mf][2 * ks + 1][2] - FIXED_M);
                float e7 = ex2f(s[mf][2 * ks + 1][3] - FIXED_M);
                lacc0[mf] += (e0 + e1) + (e4 + e5);
                lacc1[mf] += (e2 + e3) + (e6 + e7);
                bsplit2(e0, e1, ah[mf][0], al[mf][0]);
                bsplit2(e2, e3, ah[mf][1], al[mf][1]);
                bsplit2(e4, e5, ah[mf][2], al[mf][2]);
                bsplit2(e6, e7, ah[mf][3], al[mf][3]);
            }
#pragma unroll
            for (int p = 0; p < 4; p++) {
                int vrow = p * 16 + b_rl;
                uint32_t vaddr = kvb + V_OFF +
                    (uint32_t)(vrow * 128 + ((ks * 32 + b_cb) ^ ((vrow & 7) * 16)));
                uint32_t vh0, vh1, vh2, vh3, vl0, vl1, vl2, vl3;
                ldmatrix_x4(vh0, vh1, vh2, vh3, vaddr);
                ldmatrix_x4(vl0, vl1, vl2, vl3, vaddr + VL_OFF);
#pragma unroll
                for (int mf = 0; mf < 2; mf++) {
                    mma_bf16(o[mf][2 * p], ah[mf][0], ah[mf][1], ah[mf][2], ah[mf][3], vh0, vh1);
                    mma_bf16(o[mf][2 * p], ah[mf][0], ah[mf][1], ah[mf][2], ah[mf][3], vl0, vl1);
                    mma_bf16(o[mf][2 * p], al[mf][0], al[mf][1], al[mf][2], al[mf][3], vh0, vh1);
                    mma_bf16(o[mf][2 * p + 1], ah[mf][0], ah[mf][1], ah[mf][2], ah[mf][3], vh2, vh3);
                    mma_bf16(o[mf][2 * p + 1], ah[mf][0], ah[mf][1], ah[mf][2], ah[mf][3], vl2, vl3);
                    mma_bf16(o[mf][2 * p + 1], al[mf][0], al[mf][1], al[mf][2], al[mf][3], vh2, vh3);
                }
            }
        }
    }

    // ---- final l reduce (once) + epilogue (tf32-rounded) ----
#pragma unroll
    for (int mf = 0; mf < 2; mf++) {
        float su0 = lacc0[mf], su1 = lacc1[mf];
        su0 += __shfl_xor_sync(0xffffffffu, su0, 1);
        su0 += __shfl_xor_sync(0xffffffffu, su0, 2);
        su1 += __shfl_xor_sync(0xffffffffu, su1, 1);
        su1 += __shfl_xor_sync(0xffffffffu, su1, 2);
        float inv0 = 1.0f / su0;
        float inv1 = 1.0f / su1;
        int row0 = q0 + w * 32 + mf * 16 + g;
        int row1 = row0 + 8;
#pragma unroll
        for (int nf = 0; nf < 8; nf++) {
            int col = h * 64 + nf * 8 + 2 * tg;
            float2 lo;
            lo.x = __uint_as_float(f2tf32(o[mf][nf][0] * inv0));
            lo.y = __uint_as_float(f2tf32(o[mf][nf][1] * inv0));
            float2 hi;
            hi.x = __uint_as_float(f2tf32(o[mf][nf][2] * inv1));
            hi.y = __uint_as_float(f2tf32(o[mf][nf][3] * inv1));
            *reinterpret_cast<float2*>(out + (size_t)row0 * EMB + col) = lo;
            *reinterpret_cast<float2*>(out + (size_t)row1 * EMB + col) = hi;
        }
    }
}

// ===========================================================================
extern "C" void kernel_launch(void* const* d_in, const int* in_sizes, int n_in,
                              void* d_out, int out_size) {
    const float* x     = (const float*)d_in[0];   // [L, 1, E]
    const float* w_qkv = (const float*)d_in[1];   // [3E, E]
    const float* w_out = (const float*)d_in[2];   // [E, E]
    float* out = (float*)d_out;                   // [L, 1, E]

    float *qkv, *attn, *xt, *wqt, *wot;
    __nv_bfloat16 *qh, *ql, *kh, *kl, *vth, *vtl;
    cudaGetSymbolAddress((void**)&qkv, g_qkv);
    cudaGetSymbolAddress((void**)&attn, g_attn);
    cudaGetSymbolAddress((void**)&xt, g_xt);
    cudaGetSymbolAddress((void**)&wqt, g_wqt);
    cudaGetSymbolAddress((void**)&wot, g_wot);
    cudaGetSymbolAddress((void**)&qh, g_qh);
    cudaGetSymbolAddress((void**)&ql, g_ql);
    cudaGetSymbolAddress((void**)&kh, g_kh);
    cudaGetSymbolAddress((void**)&kl, g_kl);
    cudaGetSymbolAddress((void**)&vth, g_vth);
    cudaGetSymbolAddress((void**)&vtl, g_vtl);

    cudaFuncSetAttribute(gemm_mma, cudaFuncAttributeMaxDynamicSharedMemorySize, GEMM_SMEM);
    cudaFuncSetAttribute(attn_mma, cudaFuncAttributeMaxDynamicSharedMemorySize, ATT_SMEM);

    // 0) tf32 pre-rounding of gemm inputs
    tf32_round<<<(LSEQ * EMB / 4 + 255) / 256, 256>>>(x, xt, LSEQ * EMB / 4);
    tf32_round<<<(QKV3 * EMB / 4 + 255) / 256, 256>>>(w_qkv, wqt, QKV3 * EMB / 4);
    tf32_round<<<(EMB * EMB / 4 + 255) / 256, 256>>>(w_out, wot, EMB * EMB / 4);

    // 1) QKV projection (mma.sync tf32, 3-stage cp.async pipeline)
    gemm_mma<<<dim3(QKV3 / 128, LSEQ / 128), 256, GEMM_SMEM>>>(xt, wqt, qkv, LSEQ, QKV3, EMB);

    // 2) Prep: bf16 hi/lo splits (Q pre-scaled for base-2 softmax)
    prep_qk<<<(LSEQ * EMB / 4) / 256, 256>>>(qkv, qh, ql, kh, kl);
    prep_vt<<<dim3(EMB / 32, LSEQ / 32), dim3(32, 8)>>>(qkv, vth, vtl);

    // 3) Attention (fixed-offset softmax, no per-tile reductions)
    attn_mma<<<dim3(LSEQ / 128, NH), 128, ATT_SMEM>>>(qh, ql, kh, kl, vth, vtl, attn);

    // 4) Output projection
    gemm_mma<<<dim3(EMB / 128, LSEQ / 128), 256, GEMM_SMEM>>>(attn, wot, out, LSEQ, EMB, EMB);
}

// round 17
// speedup vs baseline: 1.0345x; 1.0345x over previous
#include <cuda_runtime.h>
#include <cuda_bf16.h>
#include <cstdint>
#include <math.h>

#define LSEQ 4096
#define EMB  1024
#define NH   16
#define DH   64
#define QKV3 3072

// Scratch (allocation-free rule: device globals)
__device__ float g_qkv[LSEQ * QKV3];   // [L, 3E] (only V region written now)
__device__ float g_attn[LSEQ * EMB];   // [L, E] (tf32-rounded by attn epilogue)
__device__ float g_xt[LSEQ * EMB];     // x tf32-rounded
__device__ float g_wqt[QKV3 * EMB];    // w_qkv tf32-rounded
__device__ float g_wot[EMB * EMB];     // w_out tf32-rounded
__device__ __nv_bfloat16 g_qh[LSEQ * EMB], g_ql[LSEQ * EMB];   // Q*scale*log2e hi/lo [L,E]
__device__ __nv_bfloat16 g_kh[LSEQ * EMB], g_kl[LSEQ * EMB];   // K hi/lo [L,E]
__device__ __nv_bfloat16 g_vth[EMB * LSEQ], g_vtl[EMB * LSEQ]; // V^T hi/lo [E,L]

#define QSCALE 0.18033688011112042f   // 0.125 * log2(e)

// ===========================================================================
// PTX helpers (non-'a' features only: ldmatrix / mma.sync / cp.async / cvt)
// ===========================================================================
__device__ __forceinline__ uint32_t smem_u32(const void* p) {
    uint32_t a;
    asm("{ .reg .u64 t; cvta.to.shared.u64 t, %1; cvt.u32.u64 %0, t; }" : "=r"(a) : "l"(p));
    return a;
}
__device__ __forceinline__ uint32_t f2tf32(float f) {
    uint32_t r; asm("cvt.rna.tf32.f32 %0, %1;" : "=r"(r) : "f"(f)); return r;
}
__device__ __forceinline__ float ex2f(float x) {
    float r; asm("ex2.approx.ftz.f32 %0, %1;" : "=f"(r) : "f"(x)); return r;
}
__device__ __forceinline__ void ldmatrix_x4(uint32_t& r0, uint32_t& r1, uint32_t& r2, uint32_t& r3,
                                            uint32_t addr) {
    asm volatile("ldmatrix.sync.aligned.m8n8.x4.shared.b16 {%0,%1,%2,%3}, [%4];"
                 : "=r"(r0), "=r"(r1), "=r"(r2), "=r"(r3) : "r"(addr));
}
__device__ __forceinline__ void ldmatrix_x2(uint32_t& r0, uint32_t& r1, uint32_t addr) {
    asm volatile("ldmatrix.sync.aligned.m8n8.x2.shared.b16 {%0,%1}, [%2];"
                 : "=r"(r0), "=r"(r1) : "r"(addr));
}
__device__ __forceinline__ void mma_tf32(float& c0, float& c1, float& c2, float& c3,
                                         uint32_t a0, uint32_t a1, uint32_t a2, uint32_t a3,
                                         uint32_t b0, uint32_t b1) {
    asm volatile(
        "mma.sync.aligned.m16n8k8.row.col.f32.tf32.tf32.f32 "
        "{%0,%1,%2,%3}, {%4,%5,%6,%7}, {%8,%9}, {%0,%1,%2,%3};"
        : "+f"(c0), "+f"(c1), "+f"(c2), "+f"(c3)
        : "r"(a0), "r"(a1), "r"(a2), "r"(a3), "r"(b0), "r"(b1));
}
__device__ __forceinline__ void mma_bf16(float* c,
                                         uint32_t a0, uint32_t a1, uint32_t a2, uint32_t a3,
                                         uint32_t b0, uint32_t b1) {
    asm volatile(
        "mma.sync.aligned.m16n8k16.row.col.f32.bf16.bf16.f32 "
        "{%0,%1,%2,%3}, {%4,%5,%6,%7}, {%8,%9}, {%0,%1,%2,%3};"
        : "+f"(c[0]), "+f"(c[1]), "+f"(c[2]), "+f"(c[3])
        : "r"(a0), "r"(a1), "r"(a2), "r"(a3), "r"(b0), "r"(b1));
}
__device__ __forceinline__ void bsplit(float x, __nv_bfloat16& h, __nv_bfloat16& l) {
    h = __float2bfloat16(x);
    l = __float2bfloat16(x - __bfloat162float(h));
}
__device__ __forceinline__ void bsplit2(float x0, float x1, uint32_t& hi, uint32_t& lo) {
    __nv_bfloat16 h0, l0, h1, l1;
    bsplit(x0, h0, l0);
    bsplit(x1, h1, l1);
    hi = ((uint32_t)__bfloat16_as_ushort(h1) << 16) | (uint32_t)__bfloat16_as_ushort(h0);
    lo = ((uint32_t)__bfloat16_as_ushort(l1) << 16) | (uint32_t)__bfloat16_as_ushort(l0);
}
__device__ __forceinline__ void cp16(uint32_t dst, const void* src) {
    asm volatile("cp.async.cg.shared.global [%0], [%1], 16;" :: "r"(dst), "l"(src));
}
__device__ __forceinline__ void cp_commit() {
    asm volatile("cp.async.commit_group;" ::: "memory");
}
template <int N>
__device__ __forceinline__ void cp_wait() {
    asm volatile("cp.async.wait_group %0;" :: "n"(N) : "memory");
}

// ===========================================================================
// tf32 pre-rounding: out[i] = cvt.rna.tf32(in[i]) (float4 granularity)
// ===========================================================================
__global__ __launch_bounds__(256) void tf32_round(const float* __restrict__ in,
                                                  float* __restrict__ out, int n4) {
    int idx = blockIdx.x * 256 + threadIdx.x;
    if (idx >= n4) return;
    float4 v = reinterpret_cast<const float4*>(in)[idx];
    v.x = __uint_as_float(f2tf32(v.x));
    v.y = __uint_as_float(f2tf32(v.y));
    v.z = __uint_as_float(f2tf32(v.z));
    v.w = __uint_as_float(f2tf32(v.w));
    reinterpret_cast<float4*>(out)[idx] = v;
}

// ===========================================================================
// GEMM mainloop (shared by both epilogue variants): 2-stage cp.async,
// single barrier per chunk, inputs pre-rounded to tf32.
// C[m][n] = sum_k A[m][k]*B[n][k]; 128x128 CTA tile, BK=32.
// ===========================================================================
#define GPAD 36
#define GEMM_BUF (128 * GPAD)
#define GEMM_SMEM (4 * GEMM_BUF * 4)

struct GemmCtx {
    float c[4][4][4];
    int rbase, cbase;
};

__device__ __forceinline__ void gemm_mainloop(GemmCtx& ctx,
                                              const float* __restrict__ A,
                                              const float* __restrict__ B,
                                              float* gsm, int K) {
    const int tid = threadIdx.x;
    const int t = tid & 31;
    const int wid = tid >> 5;
    const int wm = wid >> 2;
    const int wn = wid & 3;
    const int nchunks = K >> 5;
    const uint32_t sm_b = smem_u32(gsm);

    const int a_rl = (t & 7) + ((t >> 3) & 1) * 8;
    const int a_cb = ((t >> 4) & 1) * 16;
    const int b_rl = (t & 7);
    const int b_cb = ((t >> 3) & 1) * 16;

#pragma unroll
    for (int mf = 0; mf < 4; mf++)
#pragma unroll
        for (int nf = 0; nf < 4; nf++)
#pragma unroll
            for (int v = 0; v < 4; v++) ctx.c[mf][nf][v] = 0.f;

    const float* Ag = A + (size_t)ctx.rbase * K;
    const float* Bg = B + (size_t)ctx.cbase * K;

#pragma unroll
    for (int i = 0; i < 4; i++) {
        int fi = tid + i * 256;
        int row = fi >> 3, c4 = (fi & 7) << 2;
        uint32_t off = (uint32_t)((row * GPAD + c4) * 4);
        cp16(sm_b + off, Ag + (size_t)row * K + c4);
        cp16(sm_b + 2 * GEMM_BUF * 4 + off, Bg + (size_t)row * K + c4);
    }
    cp_commit();

    for (int ck = 0; ck < nchunks; ck++) {
        const int b = ck & 1;
        cp_wait<0>();
        __syncthreads();
        if (ck + 1 < nchunks) {
            const int k1 = (ck + 1) * 32;
            const uint32_t ab = sm_b + (b ^ 1) * GEMM_BUF * 4;
            const uint32_t bb = sm_b + (2 + (b ^ 1)) * GEMM_BUF * 4;
#pragma unroll
            for (int i = 0; i < 4; i++) {
                int fi = tid + i * 256;
                int row = fi >> 3, c4 = (fi & 7) << 2;
                uint32_t off = (uint32_t)((row * GPAD + c4) * 4);
                cp16(ab + off, Ag + (size_t)row * K + k1 + c4);
                cp16(bb + off, Bg + (size_t)row * K + k1 + c4);
            }
            cp_commit();
        }

        const uint32_t As_b = sm_b + b * GEMM_BUF * 4;
        const uint32_t Bs_b = sm_b + (2 + b) * GEMM_BUF * 4;
#pragma unroll
        for (int ks = 0; ks < 4; ks++) {
            uint32_t af[4][4], bf[4][2];
#pragma unroll
            for (int mf = 0; mf < 4; mf++) {
                int row = wm * 64 + mf * 16 + a_rl;
                uint32_t addr = As_b + (uint32_t)(row * GPAD * 4 + ks * 32 + a_cb);
                ldmatrix_x4(af[mf][0], af[mf][1], af[mf][2], af[mf][3], addr);
            }
#pragma unroll
            for (int nf = 0; nf < 4; nf++) {
                int row = wn * 32 + nf * 8 + b_rl;
                uint32_t addr = Bs_b + (uint32_t)(row * GPAD * 4 + ks * 32 + b_cb);
                ldmatrix_x2(bf[nf][0], bf[nf][1], addr);
            }
#pragma unroll
            for (int mf = 0; mf < 4; mf++)
#pragma unroll
                for (int nf = 0; nf < 4; nf++)
                    mma_tf32(ctx.c[mf][nf][0], ctx.c[mf][nf][1], ctx.c[mf][nf][2], ctx.c[mf][nf][3],
                             af[mf][0], af[mf][1], af[mf][2], af[mf][3],
                             bf[nf][0], bf[nf][1]);
        }
    }
}

// Plain epilogue variant (used for the output projection)
__global__ __launch_bounds__(256, 2) void gemm_mma(const float* __restrict__ A,
                                                   const float* __restrict__ B,
                                                   float* __restrict__ C,
                                                   int M, int N, int K) {
    extern __shared__ float gsm[];
    GemmCtx ctx;
    ctx.rbase = blockIdx.y * 128;
    ctx.cbase = blockIdx.x * 128;
    gemm_mainloop(ctx, A, B, gsm, K);

    const int t = threadIdx.x & 31;
    const int wid = threadIdx.x >> 5;
    const int wm = wid >> 2, wn = wid & 3;
    const int g = t >> 2, tg = t & 3;
#pragma unroll
    for (int mf = 0; mf < 4; mf++) {
        int row0 = ctx.rbase + wm * 64 + mf * 16 + g;
#pragma unroll
        for (int nf = 0; nf < 4; nf++) {
            int col = ctx.cbase + wn * 32 + nf * 8 + 2 * tg;
            float2 lo = make_float2(ctx.c[mf][nf][0], ctx.c[mf][nf][1]);
            float2 hi = make_float2(ctx.c[mf][nf][2], ctx.c[mf][nf][3]);
            *reinterpret_cast<float2*>(&C[(size_t)row0 * N + col]) = lo;
            *reinterpret_cast<float2*>(&C[(size_t)(row0 + 8) * N + col]) = hi;
        }
    }
}

// QKV epilogue variant: Q cols -> qh/ql (scaled), K cols -> kh/kl,
// V cols -> raw fp32 into g_qkv (for prep_vt). Replaces prep_qk entirely.
__global__ __launch_bounds__(256, 2) void gemm_mma_qkv(
    const float* __restrict__ A, const float* __restrict__ B,
    float* __restrict__ qkv,
    __nv_bfloat16* __restrict__ qh, __nv_bfloat16* __restrict__ ql,
    __nv_bfloat16* __restrict__ kh, __nv_bfloat16* __restrict__ kl,
    int K) {
    extern __shared__ float gsm[];
    GemmCtx ctx;
    ctx.rbase = blockIdx.y * 128;
    ctx.cbase = blockIdx.x * 128;
    gemm_mainloop(ctx, A, B, gsm, K);

    const int t = threadIdx.x & 31;
    const int wid = threadIdx.x >> 5;
    const int wm = wid >> 2, wn = wid & 3;
    const int g = t >> 2, tg = t & 3;

#pragma unroll
    for (int mf = 0; mf < 4; mf++) {
        int row0 = ctx.rbase + wm * 64 + mf * 16 + g;
        int row1 = row0 + 8;
#pragma unroll
        for (int nf = 0; nf < 4; nf++) {
            int col = ctx.cbase + wn * 32 + nf * 8 + 2 * tg;
            float v0 = ctx.c[mf][nf][0], v1 = ctx.c[mf][nf][1];
            float v2 = ctx.c[mf][nf][2], v3 = ctx.c[mf][nf][3];
            if (col < EMB) {
                // Q: scale (same fp32 op order as old prep_qk) then split
                uint32_t h01, l01, h23, l23;
                bsplit2(v0 * QSCALE, v1 * QSCALE, h01, l01);
                bsplit2(v2 * QSCALE, v3 * QSCALE, h23, l23);
                size_t o0 = (size_t)row0 * EMB + col;
                size_t o1 = (size_t)row1 * EMB + col;
                *reinterpret_cast<uint32_t*>(qh + o0) = h01;
                *reinterpret_cast<uint32_t*>(ql + o0) = l01;
                *reinterpret_cast<uint32_t*>(qh + o1) = h23;
                *reinterpret_cast<uint32_t*>(ql + o1) = l23;
            } else if (col < 2 * EMB) {
                uint32_t h01, l01, h23, l23;
                bsplit2(v0, v1, h01, l01);
                bsplit2(v2, v3, h23, l23);
                size_t o0 = (size_t)row0 * EMB + (col - EMB);
                size_t o1 = (size_t)row1 * EMB + (col - EMB);
                *reinterpret_cast<uint32_t*>(kh + o0) = h01;
                *reinterpret_cast<uint32_t*>(kl + o0) = l01;
                *reinterpret_cast<uint32_t*>(kh + o1) = h23;
                *reinterpret_cast<uint32_t*>(kl + o1) = l23;
            } else {
                // V: raw fp32 for prep_vt (unchanged layout)
                *reinterpret_cast<float2*>(&qkv[(size_t)row0 * QKV3 + col]) = make_float2(v0, v1);
                *reinterpret_cast<float2*>(&qkv[(size_t)row1 * QKV3 + col]) = make_float2(v2, v3);
            }
        }
    }
}

// ===========================================================================
// Prep: transpose V into [E, L] and split into bf16 hi/lo (unchanged)
// ===========================================================================
__global__ __launch_bounds__(256) void prep_vt(const float* __restrict__ qkv,
                                               __nv_bfloat16* __restrict__ vth,
                                               __nv_bfloat16* __restrict__ vtl) {
    __shared__ float tile[32][33];
    const int e0 = blockIdx.x * 32;
    const int l0 = blockIdx.y * 32;
    const int tx = threadIdx.x, ty = threadIdx.y;
#pragma unroll
    for (int j = 0; j < 4; j++)
        tile[ty * 4 + j][tx] = qkv[(size_t)(l0 + ty * 4 + j) * QKV3 + 2 * EMB + e0 + tx];
    __syncthreads();
#pragma unroll
    for (int j = 0; j < 4; j++) {
        float v = tile[tx][ty * 4 + j];
        __nv_bfloat16 h, lo;
        bsplit(v, h, lo);
        size_t o = (size_t)(e0 + ty * 4 + j) * LSEQ + l0 + tx;
        vth[o] = h; vtl[o] = lo;
    }
}

// ===========================================================================
// Flash attention v7 (unchanged from the 748us kernel): fixed-offset softmax,
// 4 warps x 32 Q rows, register-resident P, cp.async double-buffered KV,
// exp/bsplit interleaved into PV, single barrier per tile.
// ===========================================================================
#define S_QL_OFF 16384
#define KV_OFF   32768
#define KV_STRIDE 32768
#define KL_OFF   8192
#define V_OFF    16384
#define VL_OFF   8192
#define ATT_SMEM 98304
#define FIXED_M  40.0f

__global__ __launch_bounds__(128, 2) void attn_mma(
    const __nv_bfloat16* __restrict__ qh_g, const __nv_bfloat16* __restrict__ ql_g,
    const __nv_bfloat16* __restrict__ kh_g, const __nv_bfloat16* __restrict__ kl_g,
    const __nv_bfloat16* __restrict__ vth_g, const __nv_bfloat16* __restrict__ vtl_g,
    float* __restrict__ out) {
    extern __shared__ char sm[];
    const uint32_t sb = smem_u32(sm);
    const int tid = threadIdx.x;
    const int t = tid & 31, w = tid >> 5;
    const int h = blockIdx.y;
    const int q0 = blockIdx.x * 128;
    const int g = t >> 2, tg = t & 3;

    const int a_rl = (t & 7) + ((t >> 3) & 1) * 8;
    const int a_cb = ((t >> 4) & 1) * 16;
    const int b_rl = ((t >> 4) & 1) * 8 + (t & 7);
    const int b_cb = ((t >> 3) & 1) * 16;

    // ---- prologue: issue Q + KV tile 0 as one group ----
#pragma unroll
    for (int i = 0; i < 8; i++) {
        int slot = tid + i * 128;
        int row = slot >> 3, ch = slot & 7;
        uint32_t dst = (uint32_t)(row * 128 + ((ch * 16) ^ ((row & 7) * 16)));
        size_t src = (size_t)(q0 + row) * EMB + h * 64 + ch * 8;
        cp16(sb + dst, qh_g + src);
        cp16(sb + S_QL_OFF + dst, ql_g + src);
    }
#pragma unroll
    for (int i = 0; i < 4; i++) {
        int slot = tid + i * 128;
        int row = slot >> 3, ch = slot & 7;
        uint32_t dst = (uint32_t)(row * 128 + ((ch * 16) ^ ((row & 7) * 16)));
        size_t ksrc = (size_t)row * EMB + h * 64 + ch * 8;
        size_t vsrc = (size_t)(h * 64 + row) * LSEQ + ch * 8;
        uint32_t kb = sb + KV_OFF;
        cp16(kb + dst, kh_g + ksrc);
        cp16(kb + KL_OFF + dst, kl_g + ksrc);
        cp16(kb + V_OFF + dst, vth_g + vsrc);
        cp16(kb + V_OFF + VL_OFF + dst, vtl_g + vsrc);
    }
    cp_commit();

    float lacc0[2] = {0.f, 0.f}, lacc1[2] = {0.f, 0.f};
    float o[2][8][4];
#pragma unroll
    for (int mf = 0; mf < 2; mf++)
#pragma unroll
        for (int nf = 0; nf < 8; nf++)
#pragma unroll
            for (int v = 0; v < 4; v++) o[mf][nf][v] = 0.f;

    const int NT = LSEQ / 64;
    for (int kt = 0; kt < NT; kt++) {
        const int b = kt & 1;
        const uint32_t kvb = sb + KV_OFF + b * KV_STRIDE;

        cp_wait<0>();
        __syncthreads();
        if (kt + 1 < NT) {
            const int kv1 = (kt + 1) * 64;
            const uint32_t nb = sb + KV_OFF + (b ^ 1) * KV_STRIDE;
#pragma unroll
            for (int i = 0; i < 4; i++) {
                int slot = tid + i * 128;
                int row = slot >> 3, ch = slot & 7;
                uint32_t dst = (uint32_t)(row * 128 + ((ch * 16) ^ ((row & 7) * 16)));
                size_t ksrc = (size_t)(kv1 + row) * EMB + h * 64 + ch * 8;
                size_t vsrc = (size_t)(h * 64 + row) * LSEQ + kv1 + ch * 8;
                cp16(nb + dst, kh_g + ksrc);
                cp16(nb + KL_OFF + dst, kl_g + ksrc);
                cp16(nb + V_OFF + dst, vth_g + vsrc);
                cp16(nb + V_OFF + VL_OFF + dst, vtl_g + vsrc);
            }
            cp_commit();
        }

        // ---- S = Q K^T (3-term bf16), warp rows = w*32 .. +31 ----
        float s[2][8][4];
#pragma unroll
        for (int mf = 0; mf < 2; mf++)
#pragma unroll
            for (int nf = 0; nf < 8; nf++)
#pragma unroll
                for (int v = 0; v < 4; v++) s[mf][nf][v] = 0.f;

#pragma unroll
        for (int ks = 0; ks < 4; ks++) {
            uint32_t qh_f[2][4], ql_f[2][4];
#pragma unroll
            for (int mf = 0; mf < 2; mf++) {
                int qrow = w * 32 + mf * 16 + a_rl;
                uint32_t qaddr = sb + (uint32_t)(qrow * 128 + ((ks * 32 + a_cb) ^ ((qrow & 7) * 16)));
                ldmatrix_x4(qh_f[mf][0], qh_f[mf][1], qh_f[mf][2], qh_f[mf][3], qaddr);
                ldmatrix_x4(ql_f[mf][0], ql_f[mf][1], ql_f[mf][2], ql_f[mf][3], qaddr + S_QL_OFF);
            }
#pragma unroll
            for (int p = 0; p < 4; p++) {
                int krow = p * 16 + b_rl;
                uint32_t kaddr = kvb + (uint32_t)(krow * 128 + ((ks * 32 + b_cb) ^ ((krow & 7) * 16)));
                uint32_t kh0, kh1, kh2, kh3, klo0, klo1, klo2, klo3;
                ldmatrix_x4(kh0, kh1, kh2, kh3, kaddr);
                ldmatrix_x4(klo0, klo1, klo2, klo3, kaddr + KL_OFF);
#pragma unroll
                for (int mf = 0; mf < 2; mf++) {
                    mma_bf16(s[mf][2 * p], qh_f[mf][0], qh_f[mf][1], qh_f[mf][2], qh_f[mf][3], kh0, kh1);
                    mma_bf16(s[mf][2 * p], qh_f[mf][0], qh_f[mf][1], qh_f[mf][2], qh_f[mf][3], klo0, klo1);
                    mma_bf16(s[mf][2 * p], ql_f[mf][0], ql_f[mf][1], ql_f[mf][2], ql_f[mf][3], kh0, kh1);
                    mma_bf16(s[mf][2 * p + 1], qh_f[mf][0], qh_f[mf][1], qh_f[mf][2], qh_f[mf][3], kh2, kh3);
                    mma_bf16(s[mf][2 * p + 1], qh_f[mf][0], qh_f[mf][1], qh_f[mf][2], qh_f[mf][3], klo2, klo3);
                    mma_bf16(s[mf][2 * p + 1], ql_f[mf][0], ql_f[mf][1], ql_f[mf][2], ql_f[mf][3], kh2, kh3);
                }
            }
        }

        // ---- PV with fixed-offset exp2 interleaved per k-step ----
#pragma unroll
        for (int ks = 0; ks < 4; ks++) {
            uint32_t ah[2][4], al[2][4];
#pragma unroll
            for (int mf = 0; mf < 2; mf++) {
                float e0 = ex2f(s[mf][2 * ks][0] - FIXED_M);
                float e1 = ex2f(s[mf][2 * ks][1] - FIXED_M);
                float e2 = ex2f(s[mf][2 * ks][2] - FIXED_M);
                float e3 = ex2f(s[mf][2 * ks][3] - FIXED_M);
                float e4 = ex2f(s[mf][2 * ks + 1][0] - FIXED_M);
                float e5 = ex2f(s[mf][2 * ks + 1][1] - FIXED_M);
                float e6 = ex2f(s[mf][2 * ks + 1][2] - FIXED_M);
                float e7 = ex2f(s[mf][2 * ks + 1][3] - FIXED_M);
                lacc0[mf] += (e0 + e1) + (e4 + e5);
                lacc1[mf] += (e2 + e3) + (e6 + e7);
                bsplit2(e0, e1, ah[mf][0], al[mf][0]);
                bsplit2(e2, e3, ah[mf][1], al[mf][1]);
                bsplit2(e4, e5, ah[mf][2], al[mf][2]);
                bsplit2(e6, e7, ah[mf][3], al[mf][3]);
            }
#pragma unroll
            for (int p = 0; p < 4; p++) {
                int vrow = p * 16 + b_rl;
                uint32_t vaddr = kvb + V_OFF +
                    (uint32_t)(vrow * 128 + ((ks * 32 + b_cb) ^ ((vrow & 7) * 16)));
                uint32_t vh0, vh1, vh2, vh3, vl0, vl1, vl2, vl3;
                ldmatrix_x4(vh0, vh1, vh2, vh3, vaddr);
                ldmatrix_x4(vl0, vl1, vl2, vl3, vaddr + VL_OFF);
#pragma unroll
                for (int mf = 0; mf < 2; mf++) {
                    mma_bf16(o[mf][2 * p], ah[mf][0], ah[mf][1], ah[mf][2], ah[mf][3], vh0, vh1);
                    mma_bf16(o[mf][2 * p], ah[mf][0], ah[mf][1], ah[mf][2], ah[mf][3], vl0, vl1);
                    mma_bf16(o[mf][2 * p], al[mf][0], al[mf][1], al[mf][2], al[mf][3], vh0, vh1);
                    mma_bf16(o[mf][2 * p + 1], ah[mf][0], ah[mf][1], ah[mf][2], ah[mf][3], vh2, vh3);
                    mma_bf16(o[mf][2 * p + 1], ah[mf][0], ah[mf][1], ah[mf][2], ah[mf][3], vl2, vl3);
                    mma_bf16(o[mf][2 * p + 1], al[mf][0], al[mf][1], al[mf][2], al[mf][3], vh2, vh3);
                }
            }
        }
    }

    // ---- final l reduce (once) + epilogue (tf32-rounded) ----
#pragma unroll
    for (int mf = 0; mf < 2; mf++) {
        float su0 = lacc0[mf], su1 = lacc1[mf];
        su0 += __shfl_xor_sync(0xffffffffu, su0, 1);
        su0 += __shfl_xor_sync(0xffffffffu, su0, 2);
        su1 += __shfl_xor_sync(0xffffffffu, su1, 1);
        su1 += __shfl_xor_sync(0xffffffffu, su1, 2);
        float inv0 = 1.0f / su0;
        float inv1 = 1.0f / su1;
        int row0 = q0 + w * 32 + mf * 16 + g;
        int row1 = row0 + 8;
#pragma unroll
        for (int nf = 0; nf < 8; nf++) {
            int col = h * 64 + nf * 8 + 2 * tg;
            float2 lo;
            lo.x = __uint_as_float(f2tf32(o[mf][nf][0] * inv0));
            lo.y = __uint_as_float(f2tf32(o[mf][nf][1] * inv0));
            float2 hi;
            hi.x = __uint_as_float(f2tf32(o[mf][nf][2] * inv1));
            hi.y = __uint_as_float(f2tf32(o[mf][nf][3] * inv1));
            *reinterpret_cast<float2*>(out + (size_t)row0 * EMB + col) = lo;
            *reinterpret_cast<float2*>(out + (size_t)row1 * EMB + col) = hi;
        }
    }
}

// ===========================================================================
extern "C" void kernel_launch(void* const* d_in, const int* in_sizes, int n_in,
                              void* d_out, int out_size) {
    const float* x     = (const float*)d_in[0];   // [L, 1, E]
    const float* w_qkv = (const float*)d_in[1];   // [3E, E]
    const float* w_out = (const float*)d_in[2];   // [E, E]
    float* out = (float*)d_out;                   // [L, 1, E]

    float *qkv, *attn, *xt, *wqt, *wot;
    __nv_bfloat16 *qh, *ql, *kh, *kl, *vth, *vtl;
    cudaGetSymbolAddress((void**)&qkv, g_qkv);
    cudaGetSymbolAddress((void**)&attn, g_attn);
    cudaGetSymbolAddress((void**)&xt, g_xt);
    cudaGetSymbolAddress((void**)&wqt, g_wqt);
    cudaGetSymbolAddress((void**)&wot, g_wot);
    cudaGetSymbolAddress((void**)&qh, g_qh);
    cudaGetSymbolAddress((void**)&ql, g_ql);
    cudaGetSymbolAddress((void**)&kh, g_kh);
    cudaGetSymbolAddress((void**)&kl, g_kl);
    cudaGetSymbolAddress((void**)&vth, g_vth);
    cudaGetSymbolAddress((void**)&vtl, g_vtl);

    cudaFuncSetAttribute(gemm_mma, cudaFuncAttributeMaxDynamicSharedMemorySize, GEMM_SMEM);
    cudaFuncSetAttribute(gemm_mma_qkv, cudaFuncAttributeMaxDynamicSharedMemorySize, GEMM_SMEM);
    cudaFuncSetAttribute(attn_mma, cudaFuncAttributeMaxDynamicSharedMemorySize, ATT_SMEM);

    // 0) tf32 pre-rounding of gemm inputs
    tf32_round<<<(LSEQ * EMB / 4 + 255) / 256, 256>>>(x, xt, LSEQ * EMB / 4);
    tf32_round<<<(QKV3 * EMB / 4 + 255) / 256, 256>>>(w_qkv, wqt, QKV3 * EMB / 4);
    tf32_round<<<(EMB * EMB / 4 + 255) / 256, 256>>>(w_out, wot, EMB * EMB / 4);

    // 1) QKV projection with fused Q/K scale+split epilogue (prep_qk gone)
    gemm_mma_qkv<<<dim3(QKV3 / 128, LSEQ / 128), 256, GEMM_SMEM>>>(
        xt, wqt, qkv, qh, ql, kh, kl, EMB);

    // 2) Prep: V transpose + split only
    prep_vt<<<dim3(EMB / 32, LSEQ / 32), dim3(32, 8)>>>(qkv, vth, vtl);

    // 3) Attention (fixed-offset softmax)
    attn_mma<<<dim3(LSEQ / 128, NH), 128, ATT_SMEM>>>(qh, ql, kh, kl, vth, vtl, attn);

    // 4) Output projection
    gemm_mma<<<dim3(EMB / 128, LSEQ / 128), 256, GEMM_SMEM>>>(attn, wot, out, LSEQ, EMB, EMB);
}